// round 9
// baseline (speedup 1.0000x reference)
#include <cuda_runtime.h>

// HMM forward, fused one-hot decode + scaled recurrence — all-register design.
// B=512, T=4096, S=64, M=125. ONE warp per sequence; lane L holds the alpha
// pair (2L, 2L+1) packed f32x2 in a register. Matvec via 32x 64-bit warp
// shuffles + 64 FFMA2 against pre-swizzled A registers (no SMEM alpha, no
// barriers, no STS/LDS on the chain). Renormalize every 8 steps: Z summed
// from the shuffled operands at K==0, 1/Z applied at K==1 (linear => exact).

#define BATCH 512
#define T_LEN 4096
#define S_DIM 64
#define M_DIM 125
#define ROW_BYTES (M_DIM * 4) /* 500 */
#define WPC 4
#define THREADS (WPC * 32)

typedef unsigned long long ull;

// ---------- f32x2 helpers ----------
__device__ __forceinline__ ull pk2(float x, float y) {
    ull r; asm("mov.b64 %0, {%1, %2};" : "=l"(r) : "f"(x), "f"(y)); return r;
}
__device__ __forceinline__ void upk2(ull v, float &x, float &y) {
    asm("mov.b64 {%0, %1}, %2;" : "=f"(x), "=f"(y) : "l"(v));
}
__device__ __forceinline__ void ffma2(ull &d, ull a, ull b) {
    asm("fma.rn.f32x2 %0, %1, %2, %0;" : "+l"(d) : "l"(a), "l"(b));
}
__device__ __forceinline__ ull fadd2(ull a, ull b) {
    ull r; asm("add.rn.f32x2 %0, %1, %2;" : "=l"(r) : "l"(a), "l"(b)); return r;
}

// ---------- one-hot decode ----------
__device__ __forceinline__ float wgt(int i) {
    return ((unsigned)i < (unsigned)M_DIM) ? (float)i : 0.0f;
}
__device__ __forceinline__ int compute_obs(float4 v, int s, int lane) {
    int b0 = 4 * lane - s;
    float p;
    p = v.x * wgt(b0);
    p = fmaf(v.y, wgt(b0 + 1), p);
    p = fmaf(v.z, wgt(b0 + 2), p);
    p = fmaf(v.w, wgt(b0 + 3), p);
    return __reduce_add_sync(0xffffffffu, (int)p);
}

// 16B-aligned 512B window covering row t (row stride 500B, seq base 16B-aligned).
__device__ __forceinline__ float4 ldx4(const char* xb, int t, int lane) {
    const float4* p = (const float4*)(xb + (((size_t)(unsigned)t * ROW_BYTES) & ~(size_t)15));
    return p[lane];
}

__global__ void __launch_bounds__(THREADS, 1)
hmm_forward_kernel(const float* __restrict__ x, const float* __restrict__ I,
                   const float* __restrict__ A, const float* __restrict__ Bm,
                   float* __restrict__ out) {
    __shared__ __align__(16) float sBm[M_DIM * S_DIM];  // 32000 B

    const int lane = threadIdx.x & 31;
    const int w    = threadIdx.x >> 5;
    const int seq  = blockIdx.x * WPC + w;
    const int j0   = 2 * lane;

    // cooperative Bm -> SMEM
    {
        const float4* src = (const float4*)Bm;
        float4* dst = (float4*)sBm;
        for (int i = threadIdx.x; i < (M_DIM * S_DIM) / 4; i += blockDim.x)
            dst[i] = src[i];
    }

    // Pre-swizzled A registers (splat-free f32x2 matvec):
    // AP[s] = (A[2s][j0],   A[2s+1][j0+1])  -> accA = (even->u0, odd->u1)
    // AQ[s] = (A[2s][j0+1], A[2s+1][j0])    -> accB = (even->u1, odd->u0)
    ull AP[32], AQ[32];
#pragma unroll
    for (int s = 0; s < 32; s++) {
        float2 ra = *(const float2*)&A[(2 * s) * S_DIM + j0];
        float2 rb = *(const float2*)&A[(2 * s + 1) * S_DIM + j0];
        AP[s] = pk2(ra.x, rb.y);
        AQ[s] = pk2(ra.y, rb.x);
    }
    const float i0 = I[j0];
    const float i1 = I[j0 + 1];

    __syncthreads();  // sBm ready (only barrier in the kernel)

    const char* xb = (const char*)x + (size_t)seq * T_LEN * ROW_BYTES;

    // prime 8-deep x ring
    float4 xv[8];
#pragma unroll
    for (int r = 0; r < 8; r++) xv[r] = ldx4(xb, r, lane);

    int obs0 = compute_obs(xv[0], 0, lane);
    float2 e = *(const float2*)&sBm[obs0 * S_DIM + j0];

    float ll  = 0.0f;   // identical in all lanes
    float inv = 1.0f;   // deferred 1/Z, applied at K==1

    // ---- t = 0 : alpha = I ∘ E0 (raw), in register ----
    ull al;
    {
        xv[0] = ldx4(xb, 8, lane);
        int obsn = compute_obs(xv[1], 1, lane);
        float2 en = *(const float2*)&sBm[obsn * S_DIM + j0];
        al = pk2(i0 * e.x, i1 * e.y);
        e = en;
    }

    // Step t (K = t&7): u = (alpha A) ∘ E, all in registers.
    // K==0: Z = sum of shuffled alpha (the raw K==7 boundary) -> inv, ll.
    // K==1: multiply u by inv (one-step-deferred scaling, exact).
#define STEP(t_i, K)                                                           \
    do {                                                                       \
        const int tcur = (t_i);                                                \
        xv[(K) & 7] = ldx4(xb, min(tcur + 8, T_LEN - 1), lane);                \
        int obsn = 0;                                                          \
        if (tcur + 1 < T_LEN)                                                  \
            obsn = compute_obs(xv[((K) + 1) & 7], (tcur + 1) & 3, lane);       \
        float2 en = *(const float2*)&sBm[obsn * S_DIM + j0];                   \
        ull a0 = 0ull, a1 = 0ull, b0 = 0ull, b1 = 0ull;                        \
        ull z0 = 0ull, z1 = 0ull;                                              \
        _Pragma("unroll")                                                      \
        for (int s = 0; s < 32; s++) {                                         \
            ull av = __shfl_sync(0xffffffffu, al, s);                          \
            if (s & 1) {                                                       \
                ffma2(a1, av, AP[s]);                                          \
                ffma2(b1, av, AQ[s]);                                          \
                if ((K) == 0) z1 = fadd2(z1, av);                              \
            } else {                                                           \
                ffma2(a0, av, AP[s]);                                          \
                ffma2(b0, av, AQ[s]);                                          \
                if ((K) == 0) z0 = fadd2(z0, av);                              \
            }                                                                  \
        }                                                                      \
        if ((K) == 0) {                                                        \
            float zx, zy;                                                      \
            upk2(fadd2(z0, z1), zx, zy);                                       \
            float z = zx + zy;                                                 \
            inv = __fdividef(1.0f, z);                                         \
            ll += __logf(z);                                                   \
        }                                                                      \
        ull aa = fadd2(a0, a1), bb = fadd2(b0, b1);                            \
        float ax, ay, bx, by;                                                  \
        upk2(aa, ax, ay);                                                      \
        upk2(bb, bx, by);                                                      \
        float u0 = (ax + by) * e.x;                                            \
        float u1 = (bx + ay) * e.y;                                            \
        if ((K) == 1) { u0 *= inv; u1 *= inv; }                                \
        al = pk2(u0, u1);                                                      \
        e = en;                                                                \
    } while (0)

    // first partial block t = 1..7 (K==1 uses inv=1.0: harmless)
#pragma unroll
    for (int t = 1; t < 8; ++t) STEP(t, t);

    // full blocks; final step t=4095 (K==7) leaves raw boundary alpha in al
    for (int t0 = 8; t0 < T_LEN; t0 += 8) {
#pragma unroll
        for (int k = 0; k < 8; ++k) STEP(t0 + k, k);
    }
#undef STEP

    // epilogue: fold in the final boundary's Z = sum over all states
    {
        float ax, ay;
        upk2(al, ax, ay);
        float z = ax + ay;
        z += __shfl_xor_sync(0xffffffffu, z, 1);
        z += __shfl_xor_sync(0xffffffffu, z, 2);
        z += __shfl_xor_sync(0xffffffffu, z, 4);
        z += __shfl_xor_sync(0xffffffffu, z, 8);
        z += __shfl_xor_sync(0xffffffffu, z, 16);
        ll += __logf(z);
        if (lane == 0) out[seq] = ll;
    }
}

extern "C" void kernel_launch(void* const* d_in, const int* in_sizes, int n_in,
                              void* d_out, int out_size) {
    const float *x = nullptr, *I = nullptr, *A = nullptr, *Bm = nullptr;
    for (int i = 0; i < n_in; ++i) {
        switch (in_sizes[i]) {
            case BATCH * T_LEN * M_DIM: x  = (const float*)d_in[i]; break;
            case S_DIM:                 I  = (const float*)d_in[i]; break;
            case S_DIM * S_DIM:         A  = (const float*)d_in[i]; break;
            case M_DIM * S_DIM:         Bm = (const float*)d_in[i]; break;
            default: break;
        }
    }
    float* out = (float*)d_out;
    (void)out_size;
    hmm_forward_kernel<<<BATCH / WPC, THREADS>>>(x, I, A, Bm, out);
}

// round 12
// speedup vs baseline: 1.0536x; 1.0536x over previous
#include <cuda_runtime.h>

// HMM forward, fused one-hot decode + scaled recurrence.
// B=512, T=4096, S=64, M=125.
// ONE warp per sequence (no cross-warp sync anywhere). Lane owns output
// states (2L, 2L+1). A columns in 128 registers (f32x2 k-pair packed).
// Alpha broadcast via SMEM double buffer (+__syncwarp only).
// 12 accumulators -> FFMA2 RAW chains depth <= 6. Renormalize every 8 steps:
// Z via butterfly at K==7 (off-chain), log added there; 1/Z folded into the
// K==1 output (one-step-deferred scaling; exact by linearity).

#define BATCH 512
#define T_LEN 4096
#define S_DIM 64
#define M_DIM 125
#define ROW_BYTES (M_DIM * 4) /* 500 */
#define WPC 4
#define THREADS (WPC * 32)

typedef unsigned long long ull;

// ---------- f32x2 helpers ----------
__device__ __forceinline__ ull pk2(float x, float y) {
    ull r; asm("mov.b64 %0, {%1, %2};" : "=l"(r) : "f"(x), "f"(y)); return r;
}
__device__ __forceinline__ void upk2(ull v, float &x, float &y) {
    asm("mov.b64 {%0, %1}, %2;" : "=f"(x), "=f"(y) : "l"(v));
}
__device__ __forceinline__ void ffma2(ull &d, ull a, ull b) {
    asm("fma.rn.f32x2 %0, %1, %2, %0;" : "+l"(d) : "l"(a), "l"(b));
}
__device__ __forceinline__ ull fadd2(ull a, ull b) {
    ull r; asm("add.rn.f32x2 %0, %1, %2;" : "=l"(r) : "l"(a), "l"(b)); return r;
}

// ---------- one-hot decode ----------
__device__ __forceinline__ float wgt(int i) {
    return ((unsigned)i < (unsigned)M_DIM) ? (float)i : 0.0f;
}
__device__ __forceinline__ int compute_obs(float4 v, int s, int lane) {
    int b0 = 4 * lane - s;
    float p;
    p = v.x * wgt(b0);
    p = fmaf(v.y, wgt(b0 + 1), p);
    p = fmaf(v.z, wgt(b0 + 2), p);
    p = fmaf(v.w, wgt(b0 + 3), p);
    return __reduce_add_sync(0xffffffffu, (int)p);
}

// 16B-aligned 512B window covering row t (row stride 500B, seq base 16B-aligned).
__device__ __forceinline__ float4 ldx4(const char* xb, int t, int lane) {
    const float4* p = (const float4*)(xb + (((size_t)(unsigned)t * ROW_BYTES) & ~(size_t)15));
    return __ldcs(p + lane);  // single reader: stream, keep L1 for SMEM traffic
}

__global__ void __launch_bounds__(THREADS, 1)
hmm_forward_kernel(const float* __restrict__ x, const float* __restrict__ I,
                   const float* __restrict__ A, const float* __restrict__ Bm,
                   float* __restrict__ out) {
    __shared__ __align__(16) float sBm[M_DIM * S_DIM];     // 32000 B
    __shared__ __align__(16) float sAlpha[WPC][2][S_DIM];  // 2048 B

    const int lane = threadIdx.x & 31;
    const int w    = threadIdx.x >> 5;
    const int seq  = blockIdx.x * WPC + w;
    const int j0   = 2 * lane;

    // cooperative Bm -> SMEM
    {
        const float4* src = (const float4*)Bm;
        float4* dst = (float4*)sBm;
        for (int i = threadIdx.x; i < (M_DIM * S_DIM) / 4; i += blockDim.x)
            dst[i] = src[i];
    }

    // A columns j0, j0+1, packed over k-pairs:
    // A0[p] = (A[2p][j0],   A[2p+1][j0]);  A1[p] = same for j0+1.
    ull A0[32], A1[32];
#pragma unroll
    for (int p = 0; p < 32; p++) {
        float2 ra = *(const float2*)&A[(2 * p) * S_DIM + j0];
        float2 rb = *(const float2*)&A[(2 * p + 1) * S_DIM + j0];
        A0[p] = pk2(ra.x, rb.x);
        A1[p] = pk2(ra.y, rb.y);
    }
    const float i0 = I[j0];
    const float i1 = I[j0 + 1];

    __syncthreads();  // sBm ready (only CTA barrier in the kernel)

    const char* xb = (const char*)x + (size_t)seq * T_LEN * ROW_BYTES;

    // prime 8-deep x ring
    float4 xv[8];
#pragma unroll
    for (int r = 0; r < 8; r++) xv[r] = ldx4(xb, r, lane);

    int obs0 = compute_obs(xv[0], 0, lane);
    float2 e = *(const float2*)&sBm[obs0 * S_DIM + j0];

    float ll  = 0.0f;   // identical across lanes
    float inv = 1.0f;   // deferred 1/Z, applied at K==1

    // ---- t = 0 : u = I ∘ E0 (raw) into buffer 0 ----
    {
        xv[0] = ldx4(xb, 8, lane);
        int obsn = compute_obs(xv[1], 1, lane);
        float2 en = *(const float2*)&sBm[obsn * S_DIM + j0];
        *(float2*)&sAlpha[w][0][j0] = make_float2(i0 * e.x, i1 * e.y);
        __syncwarp();
        e = en;
    }

    // Step t (K = t&7): reads buffer (K+1)&1, writes K&1.
    // 12 accumulators: accA[6] (-> state j0), accB[6] (-> j0+1), chains <= 6.
    // K==7: z = sum(u) via butterfly (off the alpha chain; only feeds inv/ll),
    //        ll += log z here. K==1: u *= inv (deferred scaling, exact).
#define STEP(t_i, K)                                                           \
    do {                                                                       \
        const int tcur = (t_i);                                                \
        xv[(K) & 7] = ldx4(xb, min(tcur + 8, T_LEN - 1), lane);                \
        int obsn = 0;                                                          \
        if (tcur + 1 < T_LEN)                                                  \
            obsn = compute_obs(xv[((K) + 1) & 7], (tcur + 1) & 3, lane);       \
        float2 en = *(const float2*)&sBm[obsn * S_DIM + j0];                   \
        const ulonglong2* ap =                                                 \
            (const ulonglong2*)&sAlpha[w][((K) + 1) & 1][0];                   \
        ull accA[6], accB[6];                                                  \
        _Pragma("unroll")                                                      \
        for (int m = 0; m < 6; m++) { accA[m] = 0ull; accB[m] = 0ull; }        \
        _Pragma("unroll")                                                      \
        for (int q = 0; q < 16; q++) {                                         \
            ulonglong2 wv = ap[q];                                             \
            const int c = (q % 3) * 2;                                         \
            ffma2(accA[c],     wv.x, A0[2 * q]);                               \
            ffma2(accA[c + 1], wv.y, A0[2 * q + 1]);                           \
            ffma2(accB[c],     wv.x, A1[2 * q]);                               \
            ffma2(accB[c + 1], wv.y, A1[2 * q + 1]);                           \
        }                                                                      \
        ull rA0 = fadd2(accA[0], accA[1]);                                     \
        ull rA1 = fadd2(accA[2], accA[3]);                                     \
        ull rA2 = fadd2(accA[4], accA[5]);                                     \
        ull rB0 = fadd2(accB[0], accB[1]);                                     \
        ull rB1 = fadd2(accB[2], accB[3]);                                     \
        ull rB2 = fadd2(accB[4], accB[5]);                                     \
        float ax0, ay0, ax1, ay1, ax2, ay2;                                    \
        upk2(rA0, ax0, ay0); upk2(rA1, ax1, ay1); upk2(rA2, ax2, ay2);         \
        float bx0, by0, bx1, by1, bx2, by2;                                    \
        upk2(rB0, bx0, by0); upk2(rB1, bx1, by1); upk2(rB2, bx2, by2);         \
        float sA = ((ax0 + ay0) + (ax1 + ay1)) + (ax2 + ay2);                  \
        float sB = ((bx0 + by0) + (bx1 + by1)) + (bx2 + by2);                  \
        float u0 = sA * e.x;                                                   \
        float u1 = sB * e.y;                                                   \
        if ((K) == 1) { u0 *= inv; u1 *= inv; }                                \
        *(float2*)&sAlpha[w][(K) & 1][j0] = make_float2(u0, u1);               \
        __syncwarp();                                                          \
        if ((K) == 7) {                                                        \
            float z = u0 + u1;                                                 \
            z += __shfl_xor_sync(0xffffffffu, z, 1);                           \
            z += __shfl_xor_sync(0xffffffffu, z, 2);                           \
            z += __shfl_xor_sync(0xffffffffu, z, 4);                           \
            z += __shfl_xor_sync(0xffffffffu, z, 8);                           \
            z += __shfl_xor_sync(0xffffffffu, z, 16);                          \
            inv = __fdividef(1.0f, z);                                         \
            ll += __logf(z);                                                   \
        }                                                                      \
        e = en;                                                                \
    } while (0)

    // first partial block t = 1..7 (K==1 uses inv=1.0: harmless;
    // K==7 at t=7 emits the first block's log and inv)
#pragma unroll
    for (int t = 1; t < 8; ++t) STEP(t, t);

    // full blocks; K==7 at t=4095 emits the final log (its inv unused)
    for (int t0 = 8; t0 < T_LEN; t0 += 8) {
#pragma unroll
        for (int k = 0; k < 8; ++k) STEP(t0 + k, k);
    }
#undef STEP

    if (lane == 0) out[seq] = ll;
}

extern "C" void kernel_launch(void* const* d_in, const int* in_sizes, int n_in,
                              void* d_out, int out_size) {
    const float *x = nullptr, *I = nullptr, *A = nullptr, *Bm = nullptr;
    for (int i = 0; i < n_in; ++i) {
        switch (in_sizes[i]) {
            case BATCH * T_LEN * M_DIM: x  = (const float*)d_in[i]; break;
            case S_DIM:                 I  = (const float*)d_in[i]; break;
            case S_DIM * S_DIM:         A  = (const float*)d_in[i]; break;
            case M_DIM * S_DIM:         Bm = (const float*)d_in[i]; break;
            default: break;
        }
    }
    float* out = (float*)d_out;
    (void)out_size;
    hmm_forward_kernel<<<BATCH / WPC, THREADS>>>(x, I, A, Bm, out);
}

// round 14
// speedup vs baseline: 1.1748x; 1.1151x over previous
#include <cuda_runtime.h>

// HMM forward, fused one-hot decode + scaled recurrence.
// B=512, T=4096, S=64, M=125.
// ONE warp per sequence. Lane owns output states (2L, 2L+1). A columns in
// 128 registers (f32x2 k-pair packed). Alpha broadcast via SMEM double
// buffer. NO per-step barrier: loop is warp-uniform (converged), STS->LDS
// within one warp is program-ordered; compiler fenced with asm clobber.
// 12 accumulators (RAW chains <= 6). Renormalize every 8 steps: butterfly Z
// at K==7 (off-chain), 1/Z folded into K==1's emission (exact by linearity).

#define BATCH 512
#define T_LEN 4096
#define S_DIM 64
#define M_DIM 125
#define ROW_BYTES (M_DIM * 4) /* 500 */
#define WPC 4
#define THREADS (WPC * 32)

typedef unsigned long long ull;

// compiler-only ordering fence (no HW op)
#define CFENCE() asm volatile("" ::: "memory")

// ---------- f32x2 helpers ----------
__device__ __forceinline__ ull pk2(float x, float y) {
    ull r; asm("mov.b64 %0, {%1, %2};" : "=l"(r) : "f"(x), "f"(y)); return r;
}
__device__ __forceinline__ void upk2(ull v, float &x, float &y) {
    asm("mov.b64 {%0, %1}, %2;" : "=f"(x), "=f"(y) : "l"(v));
}
__device__ __forceinline__ void ffma2(ull &d, ull a, ull b) {
    asm("fma.rn.f32x2 %0, %1, %2, %0;" : "+l"(d) : "l"(a), "l"(b));
}
__device__ __forceinline__ ull fadd2(ull a, ull b) {
    ull r; asm("add.rn.f32x2 %0, %1, %2;" : "=l"(r) : "l"(a), "l"(b)); return r;
}

// ---------- one-hot decode ----------
__device__ __forceinline__ float wgt(int i) {
    return ((unsigned)i < (unsigned)M_DIM) ? (float)i : 0.0f;
}
__device__ __forceinline__ int compute_obs(float4 v, int s, int lane) {
    int b0 = 4 * lane - s;
    float p;
    p = v.x * wgt(b0);
    p = fmaf(v.y, wgt(b0 + 1), p);
    p = fmaf(v.z, wgt(b0 + 2), p);
    p = fmaf(v.w, wgt(b0 + 3), p);
    return __reduce_add_sync(0xffffffffu, (int)p);
}

// 16B-aligned 512B window covering row t (row stride 500B, seq base 16B-aligned).
__device__ __forceinline__ float4 ldx4(const char* xb, int t, int lane) {
    const float4* p = (const float4*)(xb + (((size_t)(unsigned)t * ROW_BYTES) & ~(size_t)15));
    return __ldcs(p + lane);  // single reader: stream
}

__global__ void __launch_bounds__(THREADS, 1)
hmm_forward_kernel(const float* __restrict__ x, const float* __restrict__ I,
                   const float* __restrict__ A, const float* __restrict__ Bm,
                   float* __restrict__ out) {
    __shared__ __align__(16) float sBm[M_DIM * S_DIM];     // 32000 B
    __shared__ __align__(16) float sAlpha[WPC][2][S_DIM];  // 2048 B

    const int lane = threadIdx.x & 31;
    const int w    = threadIdx.x >> 5;
    const int seq  = blockIdx.x * WPC + w;
    const int j0   = 2 * lane;

    // cooperative Bm -> SMEM
    {
        const float4* src = (const float4*)Bm;
        float4* dst = (float4*)sBm;
        for (int i = threadIdx.x; i < (M_DIM * S_DIM) / 4; i += blockDim.x)
            dst[i] = src[i];
    }

    // A columns j0, j0+1, packed over k-pairs:
    // A0[p] = (A[2p][j0],   A[2p+1][j0]);  A1[p] = same for j0+1.
    ull A0[32], A1[32];
#pragma unroll
    for (int p = 0; p < 32; p++) {
        float2 ra = *(const float2*)&A[(2 * p) * S_DIM + j0];
        float2 rb = *(const float2*)&A[(2 * p + 1) * S_DIM + j0];
        A0[p] = pk2(ra.x, rb.x);
        A1[p] = pk2(ra.y, rb.y);
    }
    const float i0 = I[j0];
    const float i1 = I[j0 + 1];

    __syncthreads();  // sBm ready (only CTA barrier; also covers t=0 below)

    const char* xb = (const char*)x + (size_t)seq * T_LEN * ROW_BYTES;

    // prime 8-deep x ring
    float4 xv[8];
#pragma unroll
    for (int r = 0; r < 8; r++) xv[r] = ldx4(xb, r, lane);

    int obs0 = compute_obs(xv[0], 0, lane);
    float2 e = *(const float2*)&sBm[obs0 * S_DIM + j0];

    float ll  = 0.0f;   // identical across lanes
    float inv = 1.0f;   // deferred 1/Z, folded into K==1 emission

    // ---- t = 0 : u = I ∘ E0 (raw) into buffer 0 ----
    {
        xv[0] = ldx4(xb, 8, lane);
        int obsn = compute_obs(xv[1], 1, lane);
        float2 en = *(const float2*)&sBm[obsn * S_DIM + j0];
        *(float2*)&sAlpha[w][0][j0] = make_float2(i0 * e.x, i1 * e.y);
        CFENCE();
        e = en;
    }

    // Step t (K = t&7): reads buffer (K+1)&1, writes K&1.
    // Warp stays converged (all control flow uniform): STS of step t-1 is
    // program-ordered before this step's LDS within the single owning warp.
    // K==1: inv folded into e BEFORE the matvec completes (off-chain FMULs).
    // K==7: z = sum(u) via butterfly (off the alpha chain), ll += log z.
#define STEP(t_i, K)                                                           \
    do {                                                                       \
        const int tcur = (t_i);                                                \
        xv[(K) & 7] = ldx4(xb, min(tcur + 8, T_LEN - 1), lane);                \
        int obsn = 0;                                                          \
        if (tcur + 1 < T_LEN)                                                  \
            obsn = compute_obs(xv[((K) + 1) & 7], (tcur + 1) & 3, lane);       \
        float2 en = *(const float2*)&sBm[obsn * S_DIM + j0];                   \
        if ((K) == 1) { e.x *= inv; e.y *= inv; }                              \
        const ulonglong2* ap =                                                 \
            (const ulonglong2*)&sAlpha[w][((K) + 1) & 1][0];                   \
        ull accA[6], accB[6];                                                  \
        _Pragma("unroll")                                                      \
        for (int m = 0; m < 6; m++) { accA[m] = 0ull; accB[m] = 0ull; }        \
        _Pragma("unroll")                                                      \
        for (int q = 0; q < 16; q++) {                                         \
            ulonglong2 wv = ap[q];                                             \
            const int c = (q % 3) * 2;                                         \
            ffma2(accA[c],     wv.x, A0[2 * q]);                               \
            ffma2(accA[c + 1], wv.y, A0[2 * q + 1]);                           \
            ffma2(accB[c],     wv.x, A1[2 * q]);                               \
            ffma2(accB[c + 1], wv.y, A1[2 * q + 1]);                           \
        }                                                                      \
        ull rA0 = fadd2(accA[0], accA[1]);                                     \
        ull rA1 = fadd2(accA[2], accA[3]);                                     \
        ull rA2 = fadd2(accA[4], accA[5]);                                     \
        ull rB0 = fadd2(accB[0], accB[1]);                                     \
        ull rB1 = fadd2(accB[2], accB[3]);                                     \
        ull rB2 = fadd2(accB[4], accB[5]);                                     \
        float ax0, ay0, ax1, ay1, ax2, ay2;                                    \
        upk2(rA0, ax0, ay0); upk2(rA1, ax1, ay1); upk2(rA2, ax2, ay2);         \
        float bx0, by0, bx1, by1, bx2, by2;                                    \
        upk2(rB0, bx0, by0); upk2(rB1, bx1, by1); upk2(rB2, bx2, by2);         \
        float sA = ((ax0 + ay0) + (ax1 + ay1)) + (ax2 + ay2);                  \
        float sB = ((bx0 + by0) + (bx1 + by1)) + (bx2 + by2);                  \
        float u0 = sA * e.x;                                                   \
        float u1 = sB * e.y;                                                   \
        *(float2*)&sAlpha[w][(K) & 1][j0] = make_float2(u0, u1);               \
        CFENCE();                                                              \
        if ((K) == 7) {                                                        \
            float z = u0 + u1;                                                 \
            z += __shfl_xor_sync(0xffffffffu, z, 1);                           \
            z += __shfl_xor_sync(0xffffffffu, z, 2);                           \
            z += __shfl_xor_sync(0xffffffffu, z, 4);                           \
            z += __shfl_xor_sync(0xffffffffu, z, 8);                           \
            z += __shfl_xor_sync(0xffffffffu, z, 16);                          \
            inv = __fdividef(1.0f, z);                                         \
            ll += __logf(z);                                                   \
        }                                                                      \
        e = en;                                                                \
    } while (0)

    // first partial block t = 1..7 (K==1 uses inv=1.0: harmless;
    // K==7 at t=7 emits the first block's log and inv)
#pragma unroll
    for (int t = 1; t < 8; ++t) STEP(t, t);

    // full blocks; K==7 at t=4095 emits the final log (its inv unused)
    for (int t0 = 8; t0 < T_LEN; t0 += 8) {
#pragma unroll
        for (int k = 0; k < 8; ++k) STEP(t0 + k, k);
    }
#undef STEP

    if (lane == 0) out[seq] = ll;
}

extern "C" void kernel_launch(void* const* d_in, const int* in_sizes, int n_in,
                              void* d_out, int out_size) {
    const float *x = nullptr, *I = nullptr, *A = nullptr, *Bm = nullptr;
    for (int i = 0; i < n_in; ++i) {
        switch (in_sizes[i]) {
            case BATCH * T_LEN * M_DIM: x  = (const float*)d_in[i]; break;
            case S_DIM:                 I  = (const float*)d_in[i]; break;
            case S_DIM * S_DIM:         A  = (const float*)d_in[i]; break;
            case M_DIM * S_DIM:         Bm = (const float*)d_in[i]; break;
            default: break;
        }
    }
    float* out = (float*)d_out;
    (void)out_size;
    hmm_forward_kernel<<<BATCH / WPC, THREADS>>>(x, I, A, Bm, out);
}